// round 1
// baseline (speedup 1.0000x reference)
#include <cuda_runtime.h>
#include <cuda_bf16.h>
#include <cstdint>

// ---------------- problem constants ----------------
#define NN   16384      // nodes
#define SS   16384      // src nodes
#define EE   262144     // edges
#define DD   512        // embed dim
#define HH   8          // heads
#define HDHD 64         // head dim
#define HID  1024       // mlp hidden
#define MLPIN 536       // D + 3*H

// ---------------- device scratch (no allocations allowed) ----------------
__device__ float g_z[(size_t)NN * DD];          // LN(att) output
__device__ float g_q[(size_t)NN * DD];
__device__ float g_k[(size_t)NN * DD];
__device__ float g_logits[(size_t)EE * HH];
__device__ float g_mmax[(size_t)NN * HH];
__device__ float g_den[(size_t)NN * HH];
__device__ float g_rowsum[(size_t)NN * HH];
__device__ float g_feat[(size_t)NN * HH * 3];
__device__ float g_mlpin[(size_t)NN * MLPIN];   // [z_mlp | feat]
__device__ float g_hid[(size_t)NN * HID];

// ---------------- helpers ----------------
__device__ __forceinline__ float gelu_tanh(float v) {
    // jax.nn.gelu default: approximate=True (tanh form)
    float u = 0.7978845608028654f * (v + 0.044715f * v * v * v);
    return 0.5f * v * (1.0f + tanhf(u));
}

__device__ __forceinline__ void atomicMaxFloat(float* addr, float val) {
    if (val >= 0.0f) atomicMax((int*)addr, __float_as_int(val));
    else             atomicMin((unsigned int*)addr, __float_as_uint(val));
}

// ---------------- init ----------------
__global__ void k_init() {
    int t = blockIdx.x * blockDim.x + threadIdx.x;
    if (t < NN * HH * 3) g_feat[t] = 0.0f;
    if (t < NN * HH) {
        g_mmax[t]   = __int_as_float(0xff800000); // -inf
        g_den[t]    = 0.0f;
        g_rowsum[t] = 0.0f;
    }
}

// ---------------- fused double layernorm ----------------
// One block per row; 128 threads, 4 elements each.
__global__ void k_ln(const float* __restrict__ x,
                     const float* __restrict__ ga, const float* __restrict__ ba,
                     const float* __restrict__ gm, const float* __restrict__ bm) {
    int n = blockIdx.x;
    int t = threadIdx.x;
    const float* xr = x + (size_t)n * DD;
    float v[4];
    float s = 0.0f, s2 = 0.0f;
#pragma unroll
    for (int i = 0; i < 4; i++) {
        v[i] = xr[t + 128 * i];
        s += v[i];
        s2 += v[i] * v[i];
    }
    // warp + block reduce
    __shared__ float shs[4], shs2[4];
#pragma unroll
    for (int o = 16; o > 0; o >>= 1) {
        s  += __shfl_xor_sync(0xffffffffu, s, o);
        s2 += __shfl_xor_sync(0xffffffffu, s2, o);
    }
    int w = t >> 5;
    if ((t & 31) == 0) { shs[w] = s; shs2[w] = s2; }
    __syncthreads();
    s  = shs[0] + shs[1] + shs[2] + shs[3];
    s2 = shs2[0] + shs2[1] + shs2[2] + shs2[3];
    float mu = s * (1.0f / DD);
    float var = s2 * (1.0f / DD) - mu * mu;
    float rstd = rsqrtf(var + 1e-5f);
#pragma unroll
    for (int i = 0; i < 4; i++) {
        int c = t + 128 * i;
        float zz = (v[i] - mu) * rstd;
        g_z[(size_t)n * DD + c]        = zz * ga[c] + ba[c];
        g_mlpin[(size_t)n * MLPIN + c] = zz * gm[c] + bm[c];
    }
}

// ---------------- generic fp32 sgemm: C[M,Nc] = A[M,K] @ B[Nc,K]^T + bias ----------------
// 128x128 tile, BK=8, 256 threads, 8x8 register microtile. Requires M%128==0,
// Nc%128==0, K%8==0 (true for all four GEMMs here: K in {512,536,1024}).
template <int ACT, bool RESID>
__device__ __forceinline__ void sgemm_body(
    const float* __restrict__ A, const float* __restrict__ B,
    const float* __restrict__ bias, const float* __restrict__ resid,
    float* __restrict__ C, int Nc, int K) {
    __shared__ float As[8][128];
    __shared__ float Bs[8][128];
    const int tid  = threadIdx.x;
    const int tx   = tid & 15;
    const int ty   = tid >> 4;
    const int lrow = tid >> 1;
    const int lcol = (tid & 1) * 4;
    const float* Ab = A + (size_t)(blockIdx.y * 128) * K;
    const float* Bb = B + (size_t)(blockIdx.x * 128) * K;

    float acc[8][8];
#pragma unroll
    for (int i = 0; i < 8; i++)
#pragma unroll
        for (int j = 0; j < 8; j++) acc[i][j] = 0.0f;

    for (int k0 = 0; k0 < K; k0 += 8) {
        float4 a4 = *(const float4*)(Ab + (size_t)lrow * K + k0 + lcol);
        float4 b4 = *(const float4*)(Bb + (size_t)lrow * K + k0 + lcol);
        __syncthreads();
        As[lcol + 0][lrow] = a4.x; As[lcol + 1][lrow] = a4.y;
        As[lcol + 2][lrow] = a4.z; As[lcol + 3][lrow] = a4.w;
        Bs[lcol + 0][lrow] = b4.x; Bs[lcol + 1][lrow] = b4.y;
        Bs[lcol + 2][lrow] = b4.z; Bs[lcol + 3][lrow] = b4.w;
        __syncthreads();
#pragma unroll
        for (int k = 0; k < 8; k++) {
            float ra[8], rb[8];
            *(float4*)&ra[0] = *(const float4*)&As[k][ty * 8];
            *(float4*)&ra[4] = *(const float4*)&As[k][ty * 8 + 4];
            *(float4*)&rb[0] = *(const float4*)&Bs[k][tx * 8];
            *(float4*)&rb[4] = *(const float4*)&Bs[k][tx * 8 + 4];
#pragma unroll
            for (int i = 0; i < 8; i++)
#pragma unroll
                for (int j = 0; j < 8; j++)
                    acc[i][j] = fmaf(ra[i], rb[j], acc[i][j]);
        }
    }
#pragma unroll
    for (int i = 0; i < 8; i++) {
        int row = blockIdx.y * 128 + ty * 8 + i;
#pragma unroll
        for (int j = 0; j < 8; j++) {
            int col = blockIdx.x * 128 + tx * 8 + j;
            float v = acc[i][j] + bias[col];
            if (ACT == 1) v = gelu_tanh(v);
            if (RESID) v += resid[(size_t)row * Nc + col];
            C[(size_t)row * Nc + col] = v;
        }
    }
}

__global__ void __launch_bounds__(256, 2) k_gemm_q(const float* Wq, const float* bq) {
    sgemm_body<0, false>(g_z, Wq, bq, nullptr, g_q, DD, DD);
}
__global__ void __launch_bounds__(256, 2) k_gemm_k(const float* Wk, const float* bk) {
    sgemm_body<0, false>(g_z, Wk, bk, nullptr, g_k, DD, DD);
}
__global__ void __launch_bounds__(256, 2) k_gemm_h(const float* W_in, const float* b_in) {
    sgemm_body<1, false>(g_mlpin, W_in, b_in, nullptr, g_hid, HID, MLPIN);
}
__global__ void __launch_bounds__(256, 2) k_gemm_o(const float* W_out, const float* b_out,
                                                   const float* x, float* out) {
    sgemm_body<0, true>(g_hid, W_out, b_out, x, out, DD, HID);
}

// ---------------- edge pass A: logits + segment max ----------------
// One warp per edge, 8 edges per block.
__global__ void k_edge_logits(const int* __restrict__ row_index,
                              const int* __restrict__ src_index,
                              const int* __restrict__ org_to_src,
                              const float* __restrict__ att_bias) {
    int e = blockIdx.x * 8 + (threadIdx.x >> 5);
    if (e >= EE) return;
    int lane = threadIdx.x & 31;
    int row = row_index[e];
    int src = org_to_src[src_index[e]];
    const float* qr = g_q + (size_t)row * DD;
    const float* kr = g_k + (size_t)src * DD;
#pragma unroll
    for (int h = 0; h < HH; h++) {
        int b = h * HDHD;
        float s = qr[b + lane] * kr[b + lane] + qr[b + 32 + lane] * kr[b + 32 + lane];
#pragma unroll
        for (int o = 16; o > 0; o >>= 1) s += __shfl_xor_sync(0xffffffffu, s, o);
        if (lane == 0) {
            float l = s * 0.125f + att_bias[(size_t)h * EE + e]; // / sqrt(64)
            g_logits[(size_t)e * HH + h] = l;
            atomicMaxFloat(&g_mmax[row * HH + h], l);
        }
    }
}

// ---------------- edge pass B: exp + accumulate (den, dist-weighted feat, rowsum) ----------------
// 1/den normalization distributes over segment sums, applied in node finalize.
__global__ void k_edge_accum(const int* __restrict__ row_index,
                             const int* __restrict__ src_index,
                             const float* __restrict__ dist,
                             const float* __restrict__ src_pos) {
    int t = blockIdx.x * blockDim.x + threadIdx.x;
    if (t >= EE * HH) return;
    int e = t >> 3;
    int h = t & 7;
    int row = row_index[e];
    float p = expf(g_logits[t] - g_mmax[row * HH + h]);
    atomicAdd(&g_den[row * HH + h], p);
    float d = dist[e];
    float w = (d == 0.0f) ? 0.0f : p / d;
    int s = src_index[e];
    float sx = src_pos[3 * s + 0];
    float sy = src_pos[3 * s + 1];
    float sz = src_pos[3 * s + 2];
    float* f = &g_feat[(size_t)row * 24 + h * 3];
    atomicAdd(f + 0, w * sx);
    atomicAdd(f + 1, w * sy);
    atomicAdd(f + 2, w * sz);
    atomicAdd(&g_rowsum[row * HH + h], w);
}

// ---------------- node finalize: feat -> mlp_in tail ----------------
__global__ void k_node_fin(const float* __restrict__ pos) {
    int t = blockIdx.x * blockDim.x + threadIdx.x;
    if (t >= NN * 24) return;
    int n = t / 24;
    int r = t % 24;
    int h = r / 3;
    int j = r % 3;
    float dn = g_den[n * HH + h];
    float inv = (dn != 0.0f) ? (1.0f / dn) : 0.0f;
    float f = g_feat[t] * inv - g_rowsum[n * HH + h] * inv * pos[n * 3 + j];
    g_mlpin[(size_t)n * MLPIN + DD + r] = f;
}

// ---------------- launch ----------------
extern "C" void kernel_launch(void* const* d_in, const int* in_sizes, int n_in,
                              void* d_out, int out_size) {
    const float* x        = (const float*)d_in[0];
    const float* Wq       = (const float*)d_in[1];
    const float* bq       = (const float*)d_in[2];
    const float* Wk       = (const float*)d_in[3];
    const float* bk       = (const float*)d_in[4];
    const float* g_att    = (const float*)d_in[5];
    const float* b_att    = (const float*)d_in[6];
    const float* g_mlp    = (const float*)d_in[7];
    const float* b_mlp    = (const float*)d_in[8];
    const float* W_in     = (const float*)d_in[9];
    const float* b_in     = (const float*)d_in[10];
    const float* W_out    = (const float*)d_in[11];
    const float* b_out    = (const float*)d_in[12];
    const float* att_bias = (const float*)d_in[13];
    const float* dist     = (const float*)d_in[14];
    const float* pos      = (const float*)d_in[15];
    const float* src_pos  = (const float*)d_in[16];
    const int*   row_index  = (const int*)d_in[17];
    const int*   src_index  = (const int*)d_in[18];
    const int*   org_to_src = (const int*)d_in[19];
    float* out = (float*)d_out;

    k_init<<<(NN * 24 + 255) / 256, 256>>>();
    k_ln<<<NN, 128>>>(x, g_att, b_att, g_mlp, b_mlp);
    k_gemm_q<<<dim3(DD / 128, NN / 128), 256>>>(Wq, bq);
    k_gemm_k<<<dim3(DD / 128, NN / 128), 256>>>(Wk, bk);
    k_edge_logits<<<EE / 8, 256>>>(row_index, src_index, org_to_src, att_bias);
    k_edge_accum<<<(EE * HH) / 256, 256>>>(row_index, src_index, dist, src_pos);
    k_node_fin<<<(NN * 24 + 255) / 256, 256>>>(pos);
    k_gemm_h<<<dim3(HID / 128, NN / 128), 256>>>(W_in, b_in);
    k_gemm_o<<<dim3(DD / 128, NN / 128), 256>>>(W_out, b_out, x, out);
}

// round 4
// speedup vs baseline: 3.7495x; 3.7495x over previous
#include <cuda_runtime.h>
#include <cuda_fp16.h>
#include <cstdint>

// ---------------- problem constants ----------------
#define NN   16384      // nodes
#define EE   262144     // edges
#define DD   512        // embed dim
#define HH   8          // heads
#define HDHD 64         // head dim
#define HID  1024       // mlp hidden
#define MLPIN 536       // D + 3*H
#define MLPIN_P 544     // padded to /32

// ---------------- device scratch (no allocations allowed) ----------------
__device__ __half g_zh[(size_t)NN * DD];         // LN(att) in fp16
__device__ __half g_mlpinh[(size_t)NN * MLPIN_P];// [z_mlp | feat | 0pad] fp16
__device__ __half g_hidh[(size_t)NN * HID];      // gelu(mlp hidden) fp16
__device__ __half g_wqh[(size_t)DD * DD];
__device__ __half g_wkh[(size_t)DD * DD];
__device__ __half g_winh[(size_t)HID * MLPIN_P];
__device__ __half g_wouth[(size_t)DD * HID];
__device__ float g_q[(size_t)NN * DD];
__device__ float g_k[(size_t)NN * DD];
__device__ float g_logits[(size_t)EE * HH];
__device__ float g_mmax[(size_t)NN * HH];
__device__ float g_den[(size_t)NN * HH];
__device__ float g_rowsum[(size_t)NN * HH];
__device__ float g_feat[(size_t)NN * HH * 3];

// ---------------- helpers ----------------
__device__ __forceinline__ uint32_t smem_u32(const void* p) {
    uint32_t a;
    asm("{ .reg .u64 t; cvta.to.shared.u64 t, %1; cvt.u32.u64 %0, t; }" : "=r"(a) : "l"(p));
    return a;
}
__device__ __forceinline__ float gelu_tanh(float v) {
    float u = 0.7978845608028654f * (v + 0.044715f * v * v * v);
    return 0.5f * v * (1.0f + tanhf(u));
}
__device__ __forceinline__ void atomicMaxFloat(float* addr, float val) {
    if (val >= 0.0f) atomicMax((int*)addr, __float_as_int(val));
    else             atomicMin((unsigned int*)addr, __float_as_uint(val));
}
__device__ __forceinline__ void ldsm_x4(uint32_t& r0, uint32_t& r1, uint32_t& r2, uint32_t& r3,
                                        uint32_t addr) {
    asm volatile("ldmatrix.sync.aligned.m8n8.x4.shared.b16 {%0,%1,%2,%3}, [%4];"
                 : "=r"(r0), "=r"(r1), "=r"(r2), "=r"(r3) : "r"(addr));
}
__device__ __forceinline__ void mma16816(float* c, const uint32_t* a, const uint32_t* b) {
    asm volatile("mma.sync.aligned.m16n8k16.row.col.f32.f16.f16.f32 "
                 "{%0,%1,%2,%3},{%4,%5,%6,%7},{%8,%9},{%0,%1,%2,%3};"
                 : "+f"(c[0]), "+f"(c[1]), "+f"(c[2]), "+f"(c[3])
                 : "r"(a[0]), "r"(a[1]), "r"(a[2]), "r"(a[3]), "r"(b[0]), "r"(b[1]));
}
__device__ __forceinline__ void cp16(uint32_t dst, const void* src) {
    asm volatile("cp.async.cg.shared.global [%0], [%1], 16;" :: "r"(dst), "l"(src));
}
#define CP_COMMIT() asm volatile("cp.async.commit_group;" ::: "memory")
#define CP_WAIT1()  asm volatile("cp.async.wait_group 1;" ::: "memory")
#define CP_WAIT0()  asm volatile("cp.async.wait_group 0;" ::: "memory")

// ---------------- init ----------------
__global__ void k_init() {
    int t = blockIdx.x * blockDim.x + threadIdx.x;
    if (t < NN * HH * 3) g_feat[t] = 0.0f;
    if (t < NN * HH) {
        g_mmax[t]   = __int_as_float(0xff800000);
        g_den[t]    = 0.0f;
        g_rowsum[t] = 0.0f;
    }
}

// ---------------- weight fp32 -> fp16 (with column pad) ----------------
__global__ void k_cvt(const float* __restrict__ src, __half* __restrict__ dst,
                      int C, int Cp, int total) {
    int t = blockIdx.x * blockDim.x + threadIdx.x;
    if (t >= total) return;
    int r = t / Cp, c = t % Cp;
    dst[t] = (c < C) ? __float2half(src[(size_t)r * C + c]) : __half(0.0f);
}

// ---------------- fused double layernorm -> fp16 outputs ----------------
__global__ void k_ln(const float* __restrict__ x,
                     const float* __restrict__ ga, const float* __restrict__ ba,
                     const float* __restrict__ gm, const float* __restrict__ bm) {
    int n = blockIdx.x;
    int t = threadIdx.x;
    const float* xr = x + (size_t)n * DD;
    float v[4];
    float s = 0.0f, s2 = 0.0f;
#pragma unroll
    for (int i = 0; i < 4; i++) {
        v[i] = xr[t + 128 * i];
        s += v[i];
        s2 += v[i] * v[i];
    }
    __shared__ float shs[4], shs2[4];
#pragma unroll
    for (int o = 16; o > 0; o >>= 1) {
        s  += __shfl_xor_sync(0xffffffffu, s, o);
        s2 += __shfl_xor_sync(0xffffffffu, s2, o);
    }
    int w = t >> 5;
    if ((t & 31) == 0) { shs[w] = s; shs2[w] = s2; }
    __syncthreads();
    s  = shs[0] + shs[1] + shs[2] + shs[3];
    s2 = shs2[0] + shs2[1] + shs2[2] + shs2[3];
    float mu = s * (1.0f / DD);
    float var = s2 * (1.0f / DD) - mu * mu;
    float rstd = rsqrtf(var + 1e-5f);
#pragma unroll
    for (int i = 0; i < 4; i++) {
        int c = t + 128 * i;
        float zz = (v[i] - mu) * rstd;
        g_zh[(size_t)n * DD + c]        = __float2half(zz * ga[c] + ba[c]);
        g_mlpinh[(size_t)n * MLPIN_P + c] = __float2half(zz * gm[c] + bm[c]);
    }
}

// ---------------- HMMA GEMM: C[M,Nc] = A[M,K] @ B[Nc,K]^T (+bias/act/resid) ----
// fp16 inputs, fp32 accum. CTA 128x128, BK=32, 8 warps (2x4), warp tile 64x32.
// SMEM padded stride 40 halves (80B) -> conflict-free ldmatrix & cp.async.
#define BM 128
#define LDT 40

template <int ACT, int RESID, int OUT16>
__global__ void __launch_bounds__(256, 2) hmma_gemm(
    const __half* __restrict__ A, const __half* __restrict__ Bw,
    const float* __restrict__ bias, const float* __restrict__ resid,
    float* __restrict__ Cf, __half* __restrict__ Ch, int K, int Nc) {
    __shared__ __half As[2][BM * LDT];
    __shared__ __half Bs[2][BM * LDT];
    const int t = threadIdx.x;
    const int lane = t & 31;
    const int w = t >> 5;
    const int wm = w >> 2;   // 0..1
    const int wn = w & 3;    // 0..3
    const __half* Ag = A  + (size_t)(blockIdx.y * 128) * K;
    const __half* Bg = Bw + (size_t)(blockIdx.x * 128) * K;
    const uint32_t sA = smem_u32(As);
    const uint32_t sB = smem_u32(Bs);

    float acc[4][4][4];
#pragma unroll
    for (int i = 0; i < 4; i++)
#pragma unroll
        for (int j = 0; j < 4; j++)
#pragma unroll
            for (int q = 0; q < 4; q++) acc[i][j][q] = 0.0f;

    const int nch = K >> 5;

    // chunk loader: 512 16B segments each for A and B; 2 per thread
#define LOAD_CHUNK(c, buf) do {                                                    \
        int _k0 = (c) << 5;                                                        \
        _Pragma("unroll")                                                          \
        for (int _s = 0; _s < 2; _s++) {                                           \
            int _seg = t + _s * 256;                                               \
            int _row = _seg >> 2, _sc = _seg & 3;                                  \
            uint32_t _off = (uint32_t)((buf) * BM * LDT + _row * LDT + _sc * 8) * 2;\
            cp16(sA + _off, Ag + (size_t)_row * K + _k0 + _sc * 8);                \
            cp16(sB + _off, Bg + (size_t)_row * K + _k0 + _sc * 8);                \
        }                                                                          \
        CP_COMMIT();                                                               \
    } while (0)

    LOAD_CHUNK(0, 0);
    for (int c = 0; c < nch; c++) {
        if (c + 1 < nch) { LOAD_CHUNK(c + 1, (c + 1) & 1); CP_WAIT1(); }
        else             { CP_WAIT0(); }
        __syncthreads();
        const int buf = c & 1;
        const uint32_t baseA = sA + (uint32_t)(buf * BM * LDT) * 2;
        const uint32_t baseB = sB + (uint32_t)(buf * BM * LDT) * 2;
#pragma unroll
        for (int ks = 0; ks < 2; ks++) {
            uint32_t a[4][4];
#pragma unroll
            for (int mf = 0; mf < 4; mf++) {
                int row = wm * 64 + mf * 16 + (lane & 15);
                int col = ks * 16 + (lane >> 4) * 8;
                ldsm_x4(a[mf][0], a[mf][1], a[mf][2], a[mf][3],
                        baseA + (uint32_t)(row * LDT + col) * 2);
            }
            uint32_t b[2][4];
#pragma unroll
            for (int nb = 0; nb < 2; nb++) {
                int row = wn * 32 + nb * 16 + (lane & 7) + ((lane >> 4) & 1) * 8;
                int col = ks * 16 + ((lane >> 3) & 1) * 8;
                ldsm_x4(b[nb][0], b[nb][1], b[nb][2], b[nb][3],
                        baseB + (uint32_t)(row * LDT + col) * 2);
            }
#pragma unroll
            for (int mf = 0; mf < 4; mf++)
#pragma unroll
                for (int nf = 0; nf < 4; nf++)
                    mma16816(acc[mf][nf], a[mf], &b[nf >> 1][(nf & 1) * 2]);
        }
        __syncthreads();
    }

    // epilogue: thread (lane) owns (row lane>>2 [+8], cols (lane&3)*2, +1)
    const int rBase = blockIdx.y * 128 + wm * 64 + (lane >> 2);
    const int cBase = blockIdx.x * 128 + wn * 32 + (lane & 3) * 2;
#pragma unroll
    for (int mf = 0; mf < 4; mf++) {
#pragma unroll
        for (int nf = 0; nf < 4; nf++) {
            const float* cc = acc[mf][nf];
            int col = cBase + nf * 8;
            float b0 = bias[col], b1 = bias[col + 1];
#pragma unroll
            for (int half = 0; half < 2; half++) {
                int row = rBase + mf * 16 + half * 8;
                float v0 = cc[half * 2 + 0] + b0;
                float v1 = cc[half * 2 + 1] + b1;
                if (ACT) { v0 = gelu_tanh(v0); v1 = gelu_tanh(v1); }
                if (RESID) {
                    const float2 r2 = *(const float2*)(resid + (size_t)row * Nc + col);
                    v0 += r2.x; v1 += r2.y;
                }
                if (OUT16) {
                    *(__half2*)(Ch + (size_t)row * Nc + col) =
                        __floats2half2_rn(v0, v1);
                } else {
                    *(float2*)(Cf + (size_t)row * Nc + col) = make_float2(v0, v1);
                }
            }
        }
    }
#undef LOAD_CHUNK
}

// ---------------- edge pass A: logits + segment max ----------------
__global__ void k_edge_logits(const int* __restrict__ row_index,
                              const int* __restrict__ src_index,
                              const int* __restrict__ org_to_src,
                              const float* __restrict__ att_bias) {
    int e = blockIdx.x * 8 + (threadIdx.x >> 5);
    if (e >= EE) return;
    int lane = threadIdx.x & 31;
    int row = row_index[e];
    int src = org_to_src[src_index[e]];
    const float* qr = g_q + (size_t)row * DD;
    const float* kr = g_k + (size_t)src * DD;
#pragma unroll
    for (int h = 0; h < HH; h++) {
        int b = h * HDHD;
        float s = qr[b + lane] * kr[b + lane] + qr[b + 32 + lane] * kr[b + 32 + lane];
#pragma unroll
        for (int o = 16; o > 0; o >>= 1) s += __shfl_xor_sync(0xffffffffu, s, o);
        if (lane == 0) {
            float l = s * 0.125f + att_bias[(size_t)h * EE + e];
            g_logits[(size_t)e * HH + h] = l;
            atomicMaxFloat(&g_mmax[row * HH + h], l);
        }
    }
}

// ---------------- edge pass B: exp + accumulate ----------------
__global__ void k_edge_accum(const int* __restrict__ row_index,
                             const int* __restrict__ src_index,
                             const float* __restrict__ dist,
                             const float* __restrict__ src_pos) {
    int t = blockIdx.x * blockDim.x + threadIdx.x;
    if (t >= EE * HH) return;
    int e = t >> 3;
    int h = t & 7;
    int row = row_index[e];
    float p = expf(g_logits[t] - g_mmax[row * HH + h]);
    atomicAdd(&g_den[row * HH + h], p);
    float d = dist[e];
    float w = (d == 0.0f) ? 0.0f : p / d;
    int s = src_index[e];
    float sx = src_pos[3 * s + 0];
    float sy = src_pos[3 * s + 1];
    float sz = src_pos[3 * s + 2];
    float* f = &g_feat[(size_t)row * 24 + h * 3];
    atomicAdd(f + 0, w * sx);
    atomicAdd(f + 1, w * sy);
    atomicAdd(f + 2, w * sz);
    atomicAdd(&g_rowsum[row * HH + h], w);
}

// ---------------- node finalize: feat -> mlp_in tail (fp16) + zero pad ----------------
__global__ void k_node_fin(const float* __restrict__ pos) {
    int t = blockIdx.x * blockDim.x + threadIdx.x;
    if (t >= NN * 32) return;
    int n = t >> 5;
    int r = t & 31;
    if (r < 24) {
        int h = r / 3;
        int j = r % 3;
        float dn = g_den[n * HH + h];
        float inv = (dn != 0.0f) ? (1.0f / dn) : 0.0f;
        float f = g_feat[n * 24 + r] * inv - g_rowsum[n * HH + h] * inv * pos[n * 3 + j];
        g_mlpinh[(size_t)n * MLPIN_P + DD + r] = __float2half(f);
    } else {
        g_mlpinh[(size_t)n * MLPIN_P + DD + r] = __half(0.0f);
    }
}

// ---------------- launch ----------------
extern "C" void kernel_launch(void* const* d_in, const int* in_sizes, int n_in,
                              void* d_out, int out_size) {
    const float* x        = (const float*)d_in[0];
    const float* Wq       = (const float*)d_in[1];
    const float* bq       = (const float*)d_in[2];
    const float* Wk       = (const float*)d_in[3];
    const float* bk       = (const float*)d_in[4];
    const float* g_att    = (const float*)d_in[5];
    const float* b_att    = (const float*)d_in[6];
    const float* g_mlp    = (const float*)d_in[7];
    const float* b_mlp    = (const float*)d_in[8];
    const float* W_in     = (const float*)d_in[9];
    const float* b_in     = (const float*)d_in[10];
    const float* W_out    = (const float*)d_in[11];
    const float* b_out    = (const float*)d_in[12];
    const float* att_bias = (const float*)d_in[13];
    const float* dist     = (const float*)d_in[14];
    const float* pos      = (const float*)d_in[15];
    const float* src_pos  = (const float*)d_in[16];
    const int*   row_index  = (const int*)d_in[17];
    const int*   src_index  = (const int*)d_in[18];
    const int*   org_to_src = (const int*)d_in[19];
    float* out = (float*)d_out;

    __half *pzh, *pmlpinh, *phidh, *pwqh, *pwkh, *pwinh, *pwouth;
    float *pq, *pk;
    cudaGetSymbolAddress((void**)&pzh, g_zh);
    cudaGetSymbolAddress((void**)&pmlpinh, g_mlpinh);
    cudaGetSymbolAddress((void**)&phidh, g_hidh);
    cudaGetSymbolAddress((void**)&pwqh, g_wqh);
    cudaGetSymbolAddress((void**)&pwkh, g_wkh);
    cudaGetSymbolAddress((void**)&pwinh, g_winh);
    cudaGetSymbolAddress((void**)&pwouth, g_wouth);
    cudaGetSymbolAddress((void**)&pq, g_q);
    cudaGetSymbolAddress((void**)&pk, g_k);

    // weight conversions (in-graph, deterministic)
    k_cvt<<<(DD * DD + 255) / 256, 256>>>(Wq, pwqh, DD, DD, DD * DD);
    k_cvt<<<(DD * DD + 255) / 256, 256>>>(Wk, pwkh, DD, DD, DD * DD);
    k_cvt<<<(HID * MLPIN_P + 255) / 256, 256>>>(W_in, pwinh, MLPIN, MLPIN_P, HID * MLPIN_P);
    k_cvt<<<(DD * HID + 255) / 256, 256>>>(W_out, pwouth, HID, HID, DD * HID);

    k_init<<<(NN * 24 + 255) / 256, 256>>>();
    k_ln<<<NN, 128>>>(x, g_att, b_att, g_mlp, b_mlp);
    // q = z @ Wq^T + bq   (fp32 out for edge kernels)
    hmma_gemm<0, 0, 0><<<dim3(DD / 128, NN / 128), 256>>>(pzh, pwqh, bq, nullptr, pq, nullptr, DD, DD);
    hmma_gemm<0, 0, 0><<<dim3(DD / 128, NN / 128), 256>>>(pzh, pwkh, bk, nullptr, pk, nullptr, DD, DD);
    k_edge_logits<<<EE / 8, 256>>>(row_index, src_index, org_to_src, att_bias);
    k_edge_accum<<<(EE * HH) / 256, 256>>>(row_index, src_index, dist, src_pos);
    k_node_fin<<<(NN * 32 + 255) / 256, 256>>>(pos);
    // hid = gelu(mlpin @ W_in^T + b_in) -> fp16
    hmma_gemm<1, 0, 1><<<dim3(HID / 128, NN / 128), 256>>>(pmlpinh, pwinh, b_in, nullptr, nullptr, phidh, MLPIN_P, HID);
    // out = x + hid @ W_out^T + b_out -> fp32
    hmma_gemm<0, 1, 0><<<dim3(DD / 128, NN / 128), 256>>>(phidh, pwouth, b_out, x, out, nullptr, HID, DD);
}